// round 4
// baseline (speedup 1.0000x reference)
#include <cuda_runtime.h>
#include <cuda_bf16.h>
#include <cstdint>

#define NN   131072
#define EE   1048576
#define HH   128
#define BBG  512
#define PPG  32
#define NH   (NN*HH)
#define NKEY (4*NN)

// ---------------- static device scratch ----------------
__device__ float g_emb[NH];
__device__ float g_h[NH];
__device__ float g_h2[NH];
__device__ float g_xinit[NH];
__device__ float g_pool[BBG * HH];
__device__ float g_tp[BBG * HH];
__device__ float g_wbt[HH * HH];
// CSR
__device__ int  g_cnt[NKEY];
__device__ int  g_off[NKEY + 1];
__device__ int  g_cur[NKEY];
__device__ int  g_bsum[512];
__device__ int2 g_rec[EE];          // {src, norm bits}

// ---------------- helpers ----------------
__device__ __forceinline__ uint32_t smem_u32(const void* p) {
    uint32_t a;
    asm("{ .reg .u64 t; cvta.to.shared.u64 t, %1; cvt.u32.u64 %0, t; }" : "=r"(a) : "l"(p));
    return a;
}
__device__ __forceinline__ void ldsm_x4(uint32_t r[4], uint32_t addr) {
    asm volatile("ldmatrix.sync.aligned.m8n8.x4.shared.b16 {%0,%1,%2,%3}, [%4];"
                 : "=r"(r[0]), "=r"(r[1]), "=r"(r[2]), "=r"(r[3]) : "r"(addr));
}
__device__ __forceinline__ void ldsm_x4_t(uint32_t r[4], uint32_t addr) {
    asm volatile("ldmatrix.sync.aligned.m8n8.x4.trans.shared.b16 {%0,%1,%2,%3}, [%4];"
                 : "=r"(r[0]), "=r"(r[1]), "=r"(r[2]), "=r"(r[3]) : "r"(addr));
}
__device__ __forceinline__ void mma_bf16(float* c, const uint32_t a[4], const uint32_t* b) {
    asm volatile(
        "mma.sync.aligned.m16n8k16.row.col.f32.bf16.bf16.f32 "
        "{%0,%1,%2,%3}, {%4,%5,%6,%7}, {%8,%9}, {%0,%1,%2,%3};"
        : "+f"(c[0]), "+f"(c[1]), "+f"(c[2]), "+f"(c[3])
        : "r"(a[0]), "r"(a[1]), "r"(a[2]), "r"(a[3]), "r"(b[0]), "r"(b[1]));
}
__device__ __forceinline__ void split2(float a, float b, uint32_t& hi, uint32_t& lo) {
    __nv_bfloat16 ha = __float2bfloat16_rn(a);
    __nv_bfloat16 hb = __float2bfloat16_rn(b);
    __nv_bfloat16 la = __float2bfloat16_rn(a - __bfloat162float(ha));
    __nv_bfloat16 lb = __float2bfloat16_rn(b - __bfloat162float(hb));
    hi = (uint32_t)__bfloat16_as_ushort(ha) | ((uint32_t)__bfloat16_as_ushort(hb) << 16);
    lo = (uint32_t)__bfloat16_as_ushort(la) | ((uint32_t)__bfloat16_as_ushort(lb) << 16);
}

// ---------------- CSR build ----------------
__global__ void k_count(const int* __restrict__ dst, const int* __restrict__ et) {
    int e = blockIdx.x * blockDim.x + threadIdx.x;
    if (e >= EE) return;
    atomicAdd(&g_cnt[et[e] * NN + dst[e]], 1);
}

__global__ void k_scan1() {   // grid 512, 256 thr; 1024 elems/block
    __shared__ int s[256];
    int t = threadIdx.x;
    int4 v = *(const int4*)(g_cnt + blockIdx.x * 1024 + t * 4);
    s[t] = v.x + v.y + v.z + v.w;
    __syncthreads();
    for (int o = 128; o > 0; o >>= 1) {
        if (t < o) s[t] += s[t + o];
        __syncthreads();
    }
    if (t == 0) g_bsum[blockIdx.x] = s[0];
}

__global__ void k_scan2() {   // 1 block, 512 thr: exclusive scan of bsum
    __shared__ int s[512];
    int t = threadIdx.x;
    int mine = g_bsum[t];
    s[t] = mine;
    __syncthreads();
    for (int o = 1; o < 512; o <<= 1) {
        int add = (t >= o) ? s[t - o] : 0;
        __syncthreads();
        s[t] += add;
        __syncthreads();
    }
    g_bsum[t] = s[t] - mine;
}

__global__ void k_scan3() {   // grid 512, 256 thr
    __shared__ int s[256];
    int t = threadIdx.x;
    int base = blockIdx.x * 1024 + t * 4;
    int4 v = *(const int4*)(g_cnt + base);
    int tsum = v.x + v.y + v.z + v.w;
    s[t] = tsum;
    __syncthreads();
    for (int o = 1; o < 256; o <<= 1) {
        int add = (t >= o) ? s[t - o] : 0;
        __syncthreads();
        s[t] += add;
        __syncthreads();
    }
    int o0 = s[t] - tsum + g_bsum[blockIdx.x];
    int o1 = o0 + v.x, o2 = o1 + v.y, o3 = o2 + v.z;
    *(int4*)(g_off + base) = make_int4(o0, o1, o2, o3);
    *(int4*)(g_cur + base) = make_int4(o0, o1, o2, o3);
    if (base + 4 == NKEY) g_off[NKEY] = o3 + v.w;
}

__global__ void k_fill(const int* __restrict__ src, const int* __restrict__ dst,
                       const int* __restrict__ et,  const float* __restrict__ norm) {
    int e = blockIdx.x * blockDim.x + threadIdx.x;
    if (e >= EE) return;
    int key = et[e] * NN + dst[e];
    int p = atomicAdd(&g_cur[key], 1);
    g_rec[p] = make_int2(src[e], __float_as_int(norm[e]));
}

// ---------------- init_forward + xinit (warp per node) ----------------
__global__ void k_init(const float4* __restrict__ tab, const int* __restrict__ gid,
                       const int* __restrict__ spo, const int* __restrict__ acc_,
                       const int* __restrict__ pre, const float* __restrict__ Wt,
                       const float* __restrict__ bt)
{
    int w    = (blockIdx.x * blockDim.x + threadIdx.x) >> 5;
    int lane = threadIdx.x & 31;
    if (w >= NN) return;
    int node = w;
    int s0 = spo[node * 3 + 0];
    int s1 = spo[node * 3 + 1];
    int s2 = spo[node * 3 + 2];
    int beg = g_off[node], end = g_off[node + 1];   // type 0 = 'ne' lists
    float4 e4;
    if ((s0 + s2) > 0 && end > beg) {
        float4 a = make_float4(0.f, 0.f, 0.f, 0.f);
        for (int i = beg; i < end; i++) {
            int2 r = g_rec[i];
            float nw = __int_as_float(r.y);
            float4 hv = tab[(size_t)gid[r.x] * 32 + lane];
            a.x += hv.x * nw; a.y += hv.y * nw;
            a.z += hv.z * nw; a.w += hv.w * nw;
        }
        e4 = a;
    } else {
        e4 = tab[(size_t)gid[node] * 32 + lane];
    }
    ((float4*)g_emb)[(size_t)node * 32 + lane] = e4;

    float coef[5];
    coef[0] = (float)s0; coef[1] = (float)s1; coef[2] = (float)s2;
    coef[3] = (float)acc_[node]; coef[4] = (float)pre[node];
    float4 r = ((const float4*)bt)[lane];
#pragma unroll
    for (int j = 0; j < 5; j++) {
        float4 ww = ((const float4*)(Wt + (size_t)(128 + j) * HH))[lane];
        r.x += coef[j] * ww.x; r.y += coef[j] * ww.y;
        r.z += coef[j] * ww.z; r.w += coef[j] * ww.w;
    }
    ((float4*)g_xinit)[(size_t)node * 32 + lane] = r;
}

// ---------------- dense HMMA GEMM (input projection) ----------------
#define SM_AHI 0
#define SM_ALO 18432
#define SM_BHI 36864
#define SM_BLO 54272
#define SM_TOT 71680

__global__ void __launch_bounds__(256, 2) k_gemm_tc(
    const float* __restrict__ A, const float* __restrict__ B, int nkc,
    const float* __restrict__ Cadd, float* __restrict__ C)
{
    extern __shared__ char smem[];
    uint32_t s0 = smem_u32(smem);
    int tid = threadIdx.x, wid = tid >> 5, lane = tid & 31;
    int row0 = blockIdx.x * 128;
    int warp_m = wid & 1, warp_n = wid >> 1;

    float c[4][4][4];
#pragma unroll
    for (int i = 0; i < 4; i++)
#pragma unroll
        for (int j = 0; j < 4; j++)
#pragma unroll
            for (int q = 0; q < 4; q++) c[i][j][q] = 0.0f;

    for (int ch = 0; ch < nkc; ch++) {
        if (tid < 128) {
            const float* ga = A + (size_t)row0 * HH + ch * 64;
#pragma unroll
            for (int p = 0; p < 16; p++) {
                int e = p * 128 + tid;
                int r = e >> 4, c4 = e & 15;
                float4 v = *(const float4*)(ga + (size_t)r * HH + c4 * 4);
                uint32_t h0, l0, h1, l1;
                split2(v.x, v.y, h0, l0);
                split2(v.z, v.w, h1, l1);
                uint32_t off = (uint32_t)r * 144 + c4 * 8;
                *(uint2*)(smem + SM_AHI + off) = make_uint2(h0, h1);
                *(uint2*)(smem + SM_ALO + off) = make_uint2(l0, l1);
            }
        } else {
            int t = tid - 128;
            const float* gb = B + (size_t)(ch * 64) * HH;
#pragma unroll
            for (int p = 0; p < 16; p++) {
                int e = p * 128 + t;
                int k = e >> 5, c4 = e & 31;
                float4 v = *(const float4*)(gb + (size_t)k * HH + c4 * 4);
                uint32_t h0, l0, h1, l1;
                split2(v.x, v.y, h0, l0);
                split2(v.z, v.w, h1, l1);
                uint32_t off = (uint32_t)k * 272 + c4 * 8;
                *(uint2*)(smem + SM_BHI + off) = make_uint2(h0, h1);
                *(uint2*)(smem + SM_BLO + off) = make_uint2(l0, l1);
            }
        }
        __syncthreads();

#pragma unroll
        for (int ks = 0; ks < 4; ks++) {
            uint32_t ah[4][4], al[4][4];
#pragma unroll
            for (int mt = 0; mt < 4; mt++) {
                uint32_t row  = warp_m * 64 + mt * 16 + (lane & 15);
                uint32_t addr = s0 + SM_AHI + row * 144 + ks * 32 + ((lane >> 4) << 4);
                ldsm_x4(ah[mt], addr);
                ldsm_x4(al[mt], addr + (SM_ALO - SM_AHI));
            }
#pragma unroll
            for (int np = 0; np < 2; np++) {
                uint32_t kk   = ks * 16 + (lane & 15);
                uint32_t col  = warp_n * 32 + np * 16 + ((lane >> 4) & 1) * 8;
                uint32_t addr = s0 + SM_BHI + kk * 272 + col * 2;
                uint32_t bh[4], bl[4];
                ldsm_x4_t(bh, addr);
                ldsm_x4_t(bl, addr + (SM_BLO - SM_BHI));
#pragma unroll
                for (int mt = 0; mt < 4; mt++) {
                    mma_bf16(c[mt][np * 2],     ah[mt], bh);
                    mma_bf16(c[mt][np * 2],     al[mt], bh);
                    mma_bf16(c[mt][np * 2],     ah[mt], bl);
                    mma_bf16(c[mt][np * 2 + 1], ah[mt], bh + 2);
                    mma_bf16(c[mt][np * 2 + 1], al[mt], bh + 2);
                    mma_bf16(c[mt][np * 2 + 1], ah[mt], bl + 2);
                }
            }
        }
        __syncthreads();
    }

#pragma unroll
    for (int mt = 0; mt < 4; mt++) {
#pragma unroll
        for (int nt = 0; nt < 4; nt++) {
            int col = warp_n * 32 + nt * 8 + (lane & 3) * 2;
#pragma unroll
            for (int half = 0; half < 2; half++) {
                long row  = row0 + warp_m * 64 + mt * 16 + (lane >> 2) + half * 8;
                long base = row * HH + col;
                float2 v;
                v.x = c[mt][nt][half * 2 + 0];
                v.y = c[mt][nt][half * 2 + 1];
                float2 t = *(const float2*)(Cadd + base);
                v.x += t.x; v.y += t.y;
                *(float2*)(C + base) = v;
            }
        }
    }
}

// ---------------- fused CSR-gather + RGCN layer GEMM ----------------
// For 128 dst rows: for each type t, A_t[row] = sum_{edges(key=t*N+node)} norm*h[src],
// then C += A_t @ W_t (3-pass bf16 split). Epilogue: +bias, relu, +resid.
#define FS_AHI 0
#define FS_ALO 34816
#define FS_BHI 69632
#define FS_BLO 104448
#define FS_TOT 139264

__global__ void __launch_bounds__(256, 1) k_gemm_fused(
    const float* __restrict__ hin, const float* __restrict__ Wl,
    const float* __restrict__ bias, const float* __restrict__ resid,
    float* __restrict__ C)
{
    extern __shared__ char smem[];
    uint32_t s0 = smem_u32(smem);
    int tid = threadIdx.x, wid = tid >> 5, lane = tid & 31;
    int row0 = blockIdx.x * 128;
    int warp_m = wid & 1, warp_n = wid >> 1;

    float c[4][4][4];
#pragma unroll
    for (int i = 0; i < 4; i++)
#pragma unroll
        for (int j = 0; j < 4; j++)
#pragma unroll
            for (int q = 0; q < 4; q++) c[i][j][q] = 0.0f;

    for (int t = 0; t < 4; t++) {
        // ---- A: CSR gather, warp handles 16 rows ----
        for (int i = 0; i < 16; i++) {
            int row  = wid * 16 + i;
            int key  = t * NN + row0 + row;
            int beg  = g_off[key], end = g_off[key + 1];
            float4 a = make_float4(0.f, 0.f, 0.f, 0.f);
            for (int e = beg; e < end; e++) {
                int2 r = g_rec[e];
                float nw = __int_as_float(r.y);
                float4 hv = *(const float4*)(hin + (size_t)r.x * HH + lane * 4);
                a.x += hv.x * nw; a.y += hv.y * nw;
                a.z += hv.z * nw; a.w += hv.w * nw;
            }
            uint32_t h0, l0, h1, l1;
            split2(a.x, a.y, h0, l0);
            split2(a.z, a.w, h1, l1);
            uint32_t off = (uint32_t)row * 272 + lane * 8;
            *(uint2*)(smem + FS_AHI + off) = make_uint2(h0, h1);
            *(uint2*)(smem + FS_ALO + off) = make_uint2(l0, l1);
        }
        // ---- B: W_t [128][128] fp32 (L2-resident) ----
        const float* gb = Wl + (size_t)t * HH * HH;
#pragma unroll
        for (int p = 0; p < 16; p++) {
            int e = p * 256 + tid;
            int k = e >> 5, c4 = e & 31;
            float4 v = *(const float4*)(gb + (size_t)k * HH + c4 * 4);
            uint32_t h0, l0, h1, l1;
            split2(v.x, v.y, h0, l0);
            split2(v.z, v.w, h1, l1);
            uint32_t off = (uint32_t)k * 272 + c4 * 8;
            *(uint2*)(smem + FS_BHI + off) = make_uint2(h0, h1);
            *(uint2*)(smem + FS_BLO + off) = make_uint2(l0, l1);
        }
        __syncthreads();

#pragma unroll
        for (int ks = 0; ks < 8; ks++) {
            uint32_t ah[4][4], al[4][4];
#pragma unroll
            for (int mt = 0; mt < 4; mt++) {
                uint32_t row  = warp_m * 64 + mt * 16 + (lane & 15);
                uint32_t addr = s0 + FS_AHI + row * 272 + ks * 32 + ((lane >> 4) << 4);
                ldsm_x4(ah[mt], addr);
                ldsm_x4(al[mt], addr + (FS_ALO - FS_AHI));
            }
#pragma unroll
            for (int np = 0; np < 2; np++) {
                uint32_t kk   = ks * 16 + (lane & 15);
                uint32_t col  = warp_n * 32 + np * 16 + ((lane >> 4) & 1) * 8;
                uint32_t addr = s0 + FS_BHI + kk * 272 + col * 2;
                uint32_t bh[4], bl[4];
                ldsm_x4_t(bh, addr);
                ldsm_x4_t(bl, addr + (FS_BLO - FS_BHI));
#pragma unroll
                for (int mt = 0; mt < 4; mt++) {
                    mma_bf16(c[mt][np * 2],     ah[mt], bh);
                    mma_bf16(c[mt][np * 2],     al[mt], bh);
                    mma_bf16(c[mt][np * 2],     ah[mt], bl);
                    mma_bf16(c[mt][np * 2 + 1], ah[mt], bh + 2);
                    mma_bf16(c[mt][np * 2 + 1], al[mt], bh + 2);
                    mma_bf16(c[mt][np * 2 + 1], ah[mt], bl + 2);
                }
            }
        }
        __syncthreads();
    }

    // ---- epilogue: +bias, relu, +resid ----
#pragma unroll
    for (int mt = 0; mt < 4; mt++) {
#pragma unroll
        for (int nt = 0; nt < 4; nt++) {
            int col = warp_n * 32 + nt * 8 + (lane & 3) * 2;
            float2 bv = *(const float2*)(bias + col);
#pragma unroll
            for (int half = 0; half < 2; half++) {
                long row  = row0 + warp_m * 64 + mt * 16 + (lane >> 2) + half * 8;
                long base = row * HH + col;
                float2 v;
                v.x = fmaxf(c[mt][nt][half * 2 + 0] + bv.x, 0.f);
                v.y = fmaxf(c[mt][nt][half * 2 + 1] + bv.y, 0.f);
                if (resid) {
                    float2 rr = *(const float2*)(resid + base);
                    v.x += rr.x; v.y += rr.y;
                }
                *(float2*)(C + base) = v;
            }
        }
    }
}

// ---------------- head kernels ----------------
__global__ void k_transpose(const float* __restrict__ Wb) {
    int idx = blockIdx.x * blockDim.x + threadIdx.x;
    if (idx >= HH * HH) return;
    int r = idx >> 7, c = idx & 127;
    g_wbt[c * HH + r] = Wb[idx];
}

__global__ void k_pool(const float* __restrict__ h, const int* __restrict__ pred) {
    int b = blockIdx.x, j = threadIdx.x;
    float acc = 0.0f;
#pragma unroll 4
    for (int p = 0; p < PPG; p++) {
        int node = pred[b * PPG + p];
        acc += h[(size_t)node * HH + j];
    }
    g_pool[b * HH + j] = acc * (1.0f / PPG);
}

__global__ void k_tp() {
    int b = blockIdx.x, hrow = threadIdx.x;
    __shared__ float ps[HH];
    ps[hrow] = g_pool[b * HH + hrow];
    __syncthreads();
    float acc = 0.0f;
#pragma unroll 8
    for (int k = 0; k < HH; k++)
        acc += g_wbt[(size_t)k * HH + hrow] * ps[k];
    g_tp[b * HH + hrow] = acc;
}

__global__ void k_score(const float* __restrict__ h, const int* __restrict__ pred,
                        const float* __restrict__ bbp, float* __restrict__ out)
{
    int b = blockIdx.x;
    int tid = threadIdx.x;
    __shared__ __align__(16) float tps[HH];
    __shared__ float sc[PPG];
    tps[tid] = g_tp[b * HH + tid];
    __syncthreads();
    int warp = tid >> 5, lane = tid & 31;
    float4 tv = ((const float4*)tps)[lane];
    for (int p = warp; p < PPG; p += 4) {
        int node = pred[b * PPG + p];
        float4 hv = ((const float4*)h)[(size_t)node * 32 + lane];
        float d = hv.x * tv.x + hv.y * tv.y + hv.z * tv.z + hv.w * tv.w;
#pragma unroll
        for (int o = 16; o > 0; o >>= 1) d += __shfl_xor_sync(0xffffffffu, d, o);
        if (lane == 0) sc[p] = d + bbp[0];
    }
    __syncthreads();
    if (tid < 32) {
        float v = sc[tid];
        float m = v;
#pragma unroll
        for (int o = 16; o > 0; o >>= 1) m = fmaxf(m, __shfl_xor_sync(0xffffffffu, m, o));
        float e = expf(v - m);
        float s = e;
#pragma unroll
        for (int o = 16; o > 0; o >>= 1) s += __shfl_xor_sync(0xffffffffu, s, o);
        out[b * PPG + tid] = v - m - logf(s);
    }
}

// ---------------- launch ----------------
extern "C" void kernel_launch(void* const* d_in, const int* in_sizes, int n_in,
                              void* d_out, int out_size)
{
    (void)in_sizes; (void)n_in; (void)out_size;
    const float* emb_table = (const float*)d_in[0];
    const float* W_t       = (const float*)d_in[1];
    const float* b_t       = (const float*)d_in[2];
    const float* W_r       = (const float*)d_in[3];
    const float* b_r       = (const float*)d_in[4];
    const float* Wb        = (const float*)d_in[5];
    const float* bb        = (const float*)d_in[6];
    const float* norm      = (const float*)d_in[7];
    const int*   gid       = (const int*)d_in[8];
    const int*   spo       = (const int*)d_in[9];
    const int*   access_   = (const int*)d_in[10];
    const int*   pre       = (const int*)d_in[11];
    const int*   src       = (const int*)d_in[12];
    const int*   dst       = (const int*)d_in[13];
    const int*   etype     = (const int*)d_in[14];
    const int*   pred      = (const int*)d_in[15];
    float* out = (float*)d_out;

    void *p_cnt, *p_emb, *p_h, *p_h2, *p_xinit;
    cudaGetSymbolAddress(&p_cnt,   g_cnt);
    cudaGetSymbolAddress(&p_emb,   g_emb);
    cudaGetSymbolAddress(&p_h,     g_h);
    cudaGetSymbolAddress(&p_h2,    g_h2);
    cudaGetSymbolAddress(&p_xinit, g_xinit);

    const int TPB = 256;
    cudaFuncSetAttribute(k_gemm_tc,    cudaFuncAttributeMaxDynamicSharedMemorySize, SM_TOT);
    cudaFuncSetAttribute(k_gemm_fused, cudaFuncAttributeMaxDynamicSharedMemorySize, FS_TOT);

    // --- CSR build ---
    cudaMemsetAsync(p_cnt, 0, (size_t)NKEY * sizeof(int), 0);
    k_count<<<EE / TPB, TPB>>>(dst, etype);
    k_scan1<<<512, 256>>>();
    k_scan2<<<1, 512>>>();
    k_scan3<<<512, 256>>>();
    k_fill<<<EE / TPB, TPB>>>(src, dst, etype, norm);

    // --- init_forward + xinit ---
    k_init<<<NN / 8, TPB>>>((const float4*)emb_table, gid, spo, access_, pre, W_t, b_t);

    // --- input projection ---
    k_gemm_tc<<<NN / 128, TPB, SM_TOT>>>((const float*)p_emb, W_t, 2,
                                         (const float*)p_xinit, (float*)p_h);

    // --- RGCN layers (fused CSR gather + GEMM) ---
    k_gemm_fused<<<NN / 128, TPB, FS_TOT>>>((const float*)p_h, W_r,
                                            b_r, (const float*)p_h, (float*)p_h2);
    k_gemm_fused<<<NN / 128, TPB, FS_TOT>>>((const float*)p_h2, W_r + 4 * HH * HH,
                                            b_r + HH, nullptr, (float*)p_h);

    // --- head ---
    k_transpose<<<(HH * HH) / TPB, TPB>>>(Wb);
    k_pool<<<BBG, HH>>>((const float*)p_h, pred);
    k_tp<<<BBG, HH>>>();
    k_score<<<BBG, HH>>>((const float*)p_h, pred, bb, out);
}

// round 5
// speedup vs baseline: 1.4344x; 1.4344x over previous
#include <cuda_runtime.h>
#include <cuda_bf16.h>
#include <cstdint>

#define NN   131072
#define EE   1048576
#define HH   128
#define BBG  512
#define PPG  32
#define NH   (NN*HH)

// ---------------- static device scratch ----------------
__device__ float g_emb[NH];        // embeddings / init-forward result
__device__ float g_h[NH];          // h0 / final h
__device__ float g_h2[NH];         // layer-0 output
__device__ float g_xinit[NH];      // xinit, then reused as agg buffer per layer
__device__ float g_m[4ULL * NH];   // y[t][N][128] (also ne-mailbox chunk 0 in init)
__device__ float g_deg[NN];
__device__ float g_pool[BBG * HH];
__device__ float g_tp[BBG * HH];
__device__ float g_wbt[HH * HH];

// ---------------- helpers ----------------
__device__ __forceinline__ uint32_t smem_u32(const void* p) {
    uint32_t a;
    asm("{ .reg .u64 t; cvta.to.shared.u64 t, %1; cvt.u32.u64 %0, t; }" : "=r"(a) : "l"(p));
    return a;
}
__device__ __forceinline__ void ldsm_x4(uint32_t r[4], uint32_t addr) {
    asm volatile("ldmatrix.sync.aligned.m8n8.x4.shared.b16 {%0,%1,%2,%3}, [%4];"
                 : "=r"(r[0]), "=r"(r[1]), "=r"(r[2]), "=r"(r[3]) : "r"(addr));
}
__device__ __forceinline__ void ldsm_x4_t(uint32_t r[4], uint32_t addr) {
    asm volatile("ldmatrix.sync.aligned.m8n8.x4.trans.shared.b16 {%0,%1,%2,%3}, [%4];"
                 : "=r"(r[0]), "=r"(r[1]), "=r"(r[2]), "=r"(r[3]) : "r"(addr));
}
__device__ __forceinline__ void mma_bf16(float* c, const uint32_t a[4], const uint32_t* b) {
    asm volatile(
        "mma.sync.aligned.m16n8k16.row.col.f32.bf16.bf16.f32 "
        "{%0,%1,%2,%3}, {%4,%5,%6,%7}, {%8,%9}, {%0,%1,%2,%3};"
        : "+f"(c[0]), "+f"(c[1]), "+f"(c[2]), "+f"(c[3])
        : "r"(a[0]), "r"(a[1]), "r"(a[2]), "r"(a[3]), "r"(b[0]), "r"(b[1]));
}
__device__ __forceinline__ void split2(float a, float b, uint32_t& hi, uint32_t& lo) {
    __nv_bfloat16 ha = __float2bfloat16_rn(a);
    __nv_bfloat16 hb = __float2bfloat16_rn(b);
    __nv_bfloat16 la = __float2bfloat16_rn(a - __bfloat162float(ha));
    __nv_bfloat16 lb = __float2bfloat16_rn(b - __bfloat162float(hb));
    hi = (uint32_t)__bfloat16_as_ushort(ha) | ((uint32_t)__bfloat16_as_ushort(hb) << 16);
    lo = (uint32_t)__bfloat16_as_ushort(la) | ((uint32_t)__bfloat16_as_ushort(lb) << 16);
}
__device__ __forceinline__ void red_add_v4(float* addr, float x, float y, float z, float w) {
    asm volatile("red.global.add.v4.f32 [%0], {%1,%2,%3,%4};"
                 :: "l"(addr), "f"(x), "f"(y), "f"(z), "f"(w) : "memory");
}

// ---------------- init_forward ----------------
__global__ void k_gather(const float4* __restrict__ tab, const int* __restrict__ gid) {
    int idx = blockIdx.x * blockDim.x + threadIdx.x;
    if (idx >= NN * 32) return;
    int node = idx >> 5;
    int f    = idx & 31;
    ((float4*)g_emb)[idx] = tab[(size_t)gid[node] * 32 + f];
}

__global__ void k_scatter_ne(const int* __restrict__ src, const int* __restrict__ dst,
                             const int* __restrict__ et,  const float* __restrict__ norm)
{
    int gw   = (blockIdx.x * blockDim.x + threadIdx.x) >> 5;
    int lane = threadIdx.x & 31;
    if (gw >= EE) return;
    if (et[gw] != 0) return;
    float w = norm[gw];
    int s = src[gw], d = dst[gw];
    float4 v = ((const float4*)g_emb)[(size_t)s * 32 + lane];
    red_add_v4(g_m + (size_t)d * HH + lane * 4, v.x * w, v.y * w, v.z * w, v.w * w);
    if (lane == 0) atomicAdd(&g_deg[d], 1.0f);
}

__global__ void k_select_xinit(const int* __restrict__ spo, const int* __restrict__ acc,
                               const int* __restrict__ pre, const float* __restrict__ Wt,
                               const float* __restrict__ bt)
{
    int idx = blockIdx.x * blockDim.x + threadIdx.x;
    if (idx >= NN * 32) return;
    int node = idx >> 5;
    int f    = idx & 31;
    int s0 = spo[node * 3 + 0];
    int s1 = spo[node * 3 + 1];
    int s2 = spo[node * 3 + 2];
    if ((s0 + s2) > 0 && g_deg[node] > 0.0f)
        ((float4*)g_emb)[idx] = ((const float4*)g_m)[idx];

    float coef[5];
    coef[0] = (float)s0; coef[1] = (float)s1; coef[2] = (float)s2;
    coef[3] = (float)acc[node]; coef[4] = (float)pre[node];
    float4 r = ((const float4*)bt)[f];
#pragma unroll
    for (int j = 0; j < 5; j++) {
        float4 w = ((const float4*)(Wt + (size_t)(128 + j) * HH))[f];
        r.x += coef[j] * w.x; r.y += coef[j] * w.y;
        r.z += coef[j] * w.z; r.w += coef[j] * w.w;
    }
    ((float4*)g_xinit)[idx] = r;
}

// ---------------- dense HMMA GEMM (input projection, K-chunks of 64) ----------------
#define SM_AHI 0
#define SM_ALO 18432
#define SM_BHI 36864
#define SM_BLO 54272
#define SM_TOT 71680

__global__ void __launch_bounds__(256, 2) k_gemm_tc(
    const float* __restrict__ A, const float* __restrict__ B, int nkc,
    const float* __restrict__ Cadd, float* __restrict__ C)
{
    extern __shared__ char smem[];
    uint32_t s0 = smem_u32(smem);
    int tid = threadIdx.x, wid = tid >> 5, lane = tid & 31;
    int row0 = blockIdx.x * 128;
    int warp_m = wid & 1, warp_n = wid >> 1;

    float c[4][4][4];
#pragma unroll
    for (int i = 0; i < 4; i++)
#pragma unroll
        for (int j = 0; j < 4; j++)
#pragma unroll
            for (int q = 0; q < 4; q++) c[i][j][q] = 0.0f;

    for (int ch = 0; ch < nkc; ch++) {
        if (tid < 128) {
            const float* ga = A + (size_t)row0 * HH + ch * 64;
#pragma unroll
            for (int p = 0; p < 16; p++) {
                int e = p * 128 + tid;
                int r = e >> 4, c4 = e & 15;
                float4 v = *(const float4*)(ga + (size_t)r * HH + c4 * 4);
                uint32_t h0, l0, h1, l1;
                split2(v.x, v.y, h0, l0);
                split2(v.z, v.w, h1, l1);
                uint32_t off = (uint32_t)r * 144 + c4 * 8;
                *(uint2*)(smem + SM_AHI + off) = make_uint2(h0, h1);
                *(uint2*)(smem + SM_ALO + off) = make_uint2(l0, l1);
            }
        } else {
            int t = tid - 128;
            const float* gb = B + (size_t)(ch * 64) * HH;
#pragma unroll
            for (int p = 0; p < 16; p++) {
                int e = p * 128 + t;
                int k = e >> 5, c4 = e & 31;
                float4 v = *(const float4*)(gb + (size_t)k * HH + c4 * 4);
                uint32_t h0, l0, h1, l1;
                split2(v.x, v.y, h0, l0);
                split2(v.z, v.w, h1, l1);
                uint32_t off = (uint32_t)k * 272 + c4 * 8;
                *(uint2*)(smem + SM_BHI + off) = make_uint2(h0, h1);
                *(uint2*)(smem + SM_BLO + off) = make_uint2(l0, l1);
            }
        }
        __syncthreads();

#pragma unroll
        for (int ks = 0; ks < 4; ks++) {
            uint32_t ah[4][4], al[4][4];
#pragma unroll
            for (int mt = 0; mt < 4; mt++) {
                uint32_t row  = warp_m * 64 + mt * 16 + (lane & 15);
                uint32_t addr = s0 + SM_AHI + row * 144 + ks * 32 + ((lane >> 4) << 4);
                ldsm_x4(ah[mt], addr);
                ldsm_x4(al[mt], addr + (SM_ALO - SM_AHI));
            }
#pragma unroll
            for (int np = 0; np < 2; np++) {
                uint32_t kk   = ks * 16 + (lane & 15);
                uint32_t col  = warp_n * 32 + np * 16 + ((lane >> 4) & 1) * 8;
                uint32_t addr = s0 + SM_BHI + kk * 272 + col * 2;
                uint32_t bh[4], bl[4];
                ldsm_x4_t(bh, addr);
                ldsm_x4_t(bl, addr + (SM_BLO - SM_BHI));
#pragma unroll
                for (int mt = 0; mt < 4; mt++) {
                    mma_bf16(c[mt][np * 2],     ah[mt], bh);
                    mma_bf16(c[mt][np * 2],     al[mt], bh);
                    mma_bf16(c[mt][np * 2],     ah[mt], bl);
                    mma_bf16(c[mt][np * 2 + 1], ah[mt], bh + 2);
                    mma_bf16(c[mt][np * 2 + 1], al[mt], bh + 2);
                    mma_bf16(c[mt][np * 2 + 1], ah[mt], bl + 2);
                }
            }
        }
        __syncthreads();
    }

#pragma unroll
    for (int mt = 0; mt < 4; mt++) {
#pragma unroll
        for (int nt = 0; nt < 4; nt++) {
            int col = warp_n * 32 + nt * 8 + (lane & 3) * 2;
#pragma unroll
            for (int half = 0; half < 2; half++) {
                long row  = row0 + warp_m * 64 + mt * 16 + (lane >> 2) + half * 8;
                long base = row * HH + col;
                float2 v;
                v.x = c[mt][nt][half * 2 + 0];
                v.y = c[mt][nt][half * 2 + 1];
                float2 t = *(const float2*)(Cadd + base);
                v.x += t.x; v.y += t.y;
                *(float2*)(C + base) = v;
            }
        }
    }
}

// ---------------- transform-first: y[t] = h @ W_r[l,t], t=0..3, A-tile loaded once ----
#define FS_AHI 0
#define FS_ALO 34816
#define FS_BHI 69632
#define FS_BLO 104448
#define FS_TOT 139264

__global__ void __launch_bounds__(256, 1) k_gemm4(
    const float* __restrict__ A, const float* __restrict__ Wl, float* __restrict__ y)
{
    extern __shared__ char smem[];
    uint32_t s0 = smem_u32(smem);
    int tid = threadIdx.x, wid = tid >> 5, lane = tid & 31;
    int row0 = blockIdx.x * 128;
    int warp_m = wid & 1, warp_n = wid >> 1;

    // A tile [128][128] fp32 -> hi/lo bf16, 272B row stride, loaded ONCE
    {
        const float* ga = A + (size_t)row0 * HH;
#pragma unroll
        for (int p = 0; p < 16; p++) {
            int e = p * 256 + tid;
            int r = e >> 5, c4 = e & 31;
            float4 v = *(const float4*)(ga + (size_t)r * HH + c4 * 4);
            uint32_t h0, l0, h1, l1;
            split2(v.x, v.y, h0, l0);
            split2(v.z, v.w, h1, l1);
            uint32_t off = (uint32_t)r * 272 + c4 * 8;
            *(uint2*)(smem + FS_AHI + off) = make_uint2(h0, h1);
            *(uint2*)(smem + FS_ALO + off) = make_uint2(l0, l1);
        }
    }
    __syncthreads();

    for (int t = 0; t < 4; t++) {
        // B_t [128][128]
        const float* gb = Wl + (size_t)t * HH * HH;
#pragma unroll
        for (int p = 0; p < 16; p++) {
            int e = p * 256 + tid;
            int k = e >> 5, c4 = e & 31;
            float4 v = *(const float4*)(gb + (size_t)k * HH + c4 * 4);
            uint32_t h0, l0, h1, l1;
            split2(v.x, v.y, h0, l0);
            split2(v.z, v.w, h1, l1);
            uint32_t off = (uint32_t)k * 272 + c4 * 8;
            *(uint2*)(smem + FS_BHI + off) = make_uint2(h0, h1);
            *(uint2*)(smem + FS_BLO + off) = make_uint2(l0, l1);
        }
        __syncthreads();

        float c[4][4][4];
#pragma unroll
        for (int i = 0; i < 4; i++)
#pragma unroll
            for (int j = 0; j < 4; j++)
#pragma unroll
                for (int q = 0; q < 4; q++) c[i][j][q] = 0.0f;

#pragma unroll
        for (int ks = 0; ks < 8; ks++) {
            uint32_t ah[4][4], al[4][4];
#pragma unroll
            for (int mt = 0; mt < 4; mt++) {
                uint32_t row  = warp_m * 64 + mt * 16 + (lane & 15);
                uint32_t addr = s0 + FS_AHI + row * 272 + ks * 32 + ((lane >> 4) << 4);
                ldsm_x4(ah[mt], addr);
                ldsm_x4(al[mt], addr + (FS_ALO - FS_AHI));
            }
#pragma unroll
            for (int np = 0; np < 2; np++) {
                uint32_t kk   = ks * 16 + (lane & 15);
                uint32_t col  = warp_n * 32 + np * 16 + ((lane >> 4) & 1) * 8;
                uint32_t addr = s0 + FS_BHI + kk * 272 + col * 2;
                uint32_t bh[4], bl[4];
                ldsm_x4_t(bh, addr);
                ldsm_x4_t(bl, addr + (FS_BLO - FS_BHI));
#pragma unroll
                for (int mt = 0; mt < 4; mt++) {
                    mma_bf16(c[mt][np * 2],     ah[mt], bh);
                    mma_bf16(c[mt][np * 2],     al[mt], bh);
                    mma_bf16(c[mt][np * 2],     ah[mt], bl);
                    mma_bf16(c[mt][np * 2 + 1], ah[mt], bh + 2);
                    mma_bf16(c[mt][np * 2 + 1], al[mt], bh + 2);
                    mma_bf16(c[mt][np * 2 + 1], ah[mt], bl + 2);
                }
            }
        }

        // write y_t
        float* Ct = y + (size_t)t * NH;
#pragma unroll
        for (int mt = 0; mt < 4; mt++) {
#pragma unroll
            for (int nt = 0; nt < 4; nt++) {
                int col = warp_n * 32 + nt * 8 + (lane & 3) * 2;
#pragma unroll
                for (int half = 0; half < 2; half++) {
                    long row  = row0 + warp_m * 64 + mt * 16 + (lane >> 2) + half * 8;
                    long base = row * HH + col;
                    *(float2*)(Ct + base) =
                        make_float2(c[mt][nt][half * 2 + 0], c[mt][nt][half * 2 + 1]);
                }
            }
        }
        __syncthreads();   // protect B smem before next type's load
    }
}

// ---------------- scatter y_{etype}[src]*norm into agg[dst] (64MB, L2-resident) ----
__global__ void k_scatter_y(const float* __restrict__ y, float* __restrict__ agg,
                            const int* __restrict__ src, const int* __restrict__ dst,
                            const int* __restrict__ et,  const float* __restrict__ norm)
{
    int gw   = (blockIdx.x * blockDim.x + threadIdx.x) >> 5;
    int lane = threadIdx.x & 31;
    if (gw >= EE) return;
    int t = et[gw];
    float w = norm[gw];
    int s = src[gw], d = dst[gw];
    float4 v = *(const float4*)(y + (size_t)t * NH + (size_t)s * HH + lane * 4);
    red_add_v4(agg + (size_t)d * HH + lane * 4, v.x * w, v.y * w, v.z * w, v.w * w);
}

// ---------------- finish: h_next = relu(agg + b) (+ resid) ----------------
__global__ void k_finish(const float* __restrict__ agg, const float* __restrict__ bias,
                         const float* __restrict__ resid, float* __restrict__ out)
{
    int idx = blockIdx.x * blockDim.x + threadIdx.x;
    if (idx >= NN * 32) return;
    int f = idx & 31;
    float4 a = ((const float4*)agg)[idx];
    float4 b = ((const float4*)bias)[f];
    float4 v;
    v.x = fmaxf(a.x + b.x, 0.f);
    v.y = fmaxf(a.y + b.y, 0.f);
    v.z = fmaxf(a.z + b.z, 0.f);
    v.w = fmaxf(a.w + b.w, 0.f);
    if (resid) {
        float4 r = ((const float4*)resid)[idx];
        v.x += r.x; v.y += r.y; v.z += r.z; v.w += r.w;
    }
    ((float4*)out)[idx] = v;
}

// ---------------- head kernels ----------------
__global__ void k_transpose(const float* __restrict__ Wb) {
    int idx = blockIdx.x * blockDim.x + threadIdx.x;
    if (idx >= HH * HH) return;
    int r = idx >> 7, c = idx & 127;
    g_wbt[c * HH + r] = Wb[idx];
}

__global__ void k_pool(const float* __restrict__ h, const int* __restrict__ pred) {
    int b = blockIdx.x, j = threadIdx.x;
    float acc = 0.0f;
#pragma unroll 4
    for (int p = 0; p < PPG; p++) {
        int node = pred[b * PPG + p];
        acc += h[(size_t)node * HH + j];
    }
    g_pool[b * HH + j] = acc * (1.0f / PPG);
}

__global__ void k_tp() {
    int b = blockIdx.x, hrow = threadIdx.x;
    __shared__ float ps[HH];
    ps[hrow] = g_pool[b * HH + hrow];
    __syncthreads();
    float acc = 0.0f;
#pragma unroll 8
    for (int k = 0; k < HH; k++)
        acc += g_wbt[(size_t)k * HH + hrow] * ps[k];
    g_tp[b * HH + hrow] = acc;
}

__global__ void k_score(const float* __restrict__ h, const int* __restrict__ pred,
                        const float* __restrict__ bbp, float* __restrict__ out)
{
    int b = blockIdx.x;
    int tid = threadIdx.x;
    __shared__ __align__(16) float tps[HH];
    __shared__ float sc[PPG];
    tps[tid] = g_tp[b * HH + tid];
    __syncthreads();
    int warp = tid >> 5, lane = tid & 31;
    float4 tv = ((const float4*)tps)[lane];
    for (int p = warp; p < PPG; p += 4) {
        int node = pred[b * PPG + p];
        float4 hv = ((const float4*)h)[(size_t)node * 32 + lane];
        float d = hv.x * tv.x + hv.y * tv.y + hv.z * tv.z + hv.w * tv.w;
#pragma unroll
        for (int o = 16; o > 0; o >>= 1) d += __shfl_xor_sync(0xffffffffu, d, o);
        if (lane == 0) sc[p] = d + bbp[0];
    }
    __syncthreads();
    if (tid < 32) {
        float v = sc[tid];
        float m = v;
#pragma unroll
        for (int o = 16; o > 0; o >>= 1) m = fmaxf(m, __shfl_xor_sync(0xffffffffu, m, o));
        float e = expf(v - m);
        float s = e;
#pragma unroll
        for (int o = 16; o > 0; o >>= 1) s += __shfl_xor_sync(0xffffffffu, s, o);
        out[b * PPG + tid] = v - m - logf(s);
    }
}

// ---------------- launch ----------------
extern "C" void kernel_launch(void* const* d_in, const int* in_sizes, int n_in,
                              void* d_out, int out_size)
{
    (void)in_sizes; (void)n_in; (void)out_size;
    const float* emb_table = (const float*)d_in[0];
    const float* W_t       = (const float*)d_in[1];
    const float* b_t       = (const float*)d_in[2];
    const float* W_r       = (const float*)d_in[3];
    const float* b_r       = (const float*)d_in[4];
    const float* Wb        = (const float*)d_in[5];
    const float* bb        = (const float*)d_in[6];
    const float* norm      = (const float*)d_in[7];
    const int*   gid       = (const int*)d_in[8];
    const int*   spo       = (const int*)d_in[9];
    const int*   access_   = (const int*)d_in[10];
    const int*   pre       = (const int*)d_in[11];
    const int*   src       = (const int*)d_in[12];
    const int*   dst       = (const int*)d_in[13];
    const int*   etype     = (const int*)d_in[14];
    const int*   pred      = (const int*)d_in[15];
    float* out = (float*)d_out;

    void *p_m, *p_deg, *p_emb, *p_h, *p_h2, *p_xinit;
    cudaGetSymbolAddress(&p_m,     g_m);
    cudaGetSymbolAddress(&p_deg,   g_deg);
    cudaGetSymbolAddress(&p_emb,   g_emb);
    cudaGetSymbolAddress(&p_h,     g_h);
    cudaGetSymbolAddress(&p_h2,    g_h2);
    cudaGetSymbolAddress(&p_xinit, g_xinit);

    const int TPB = 256;
    const int gather_blocks  = (NN * 32) / TPB;
    const int scatter_blocks = (EE * 32) / TPB;
    const int gemm_blocks    = NN / 128;

    cudaFuncSetAttribute(k_gemm_tc, cudaFuncAttributeMaxDynamicSharedMemorySize, SM_TOT);
    cudaFuncSetAttribute(k_gemm4,   cudaFuncAttributeMaxDynamicSharedMemorySize, FS_TOT);

    // --- init_forward ---
    cudaMemsetAsync(p_m,   0, (size_t)NH * sizeof(float), 0);
    cudaMemsetAsync(p_deg, 0, (size_t)NN * sizeof(float), 0);
    k_gather<<<gather_blocks, TPB>>>((const float4*)emb_table, gid);
    k_scatter_ne<<<scatter_blocks, TPB>>>(src, dst, etype, norm);
    k_select_xinit<<<gather_blocks, TPB>>>(spo, access_, pre, W_t, b_t);

    // --- input projection: h0 = emb @ W_t[:128] + xinit ---
    k_gemm_tc<<<gemm_blocks, TPB, SM_TOT>>>((const float*)p_emb, W_t, 2,
                                            (const float*)p_xinit, (float*)p_h);

    // --- layer 0: transform-first ---
    k_gemm4<<<gemm_blocks, TPB, FS_TOT>>>((const float*)p_h, W_r, (float*)p_m);
    cudaMemsetAsync(p_xinit, 0, (size_t)NH * sizeof(float), 0);
    k_scatter_y<<<scatter_blocks, TPB>>>((const float*)p_m, (float*)p_xinit,
                                         src, dst, etype, norm);
    k_finish<<<gather_blocks, TPB>>>((const float*)p_xinit, b_r,
                                     (const float*)p_h, (float*)p_h2);

    // --- layer 1 ---
    k_gemm4<<<gemm_blocks, TPB, FS_TOT>>>((const float*)p_h2, W_r + 4 * HH * HH, (float*)p_m);
    cudaMemsetAsync(p_xinit, 0, (size_t)NH * sizeof(float), 0);
    k_scatter_y<<<scatter_blocks, TPB>>>((const float*)p_m, (float*)p_xinit,
                                         src, dst, etype, norm);
    k_finish<<<gather_blocks, TPB>>>((const float*)p_xinit, b_r + HH,
                                     nullptr, (float*)p_h);

    // --- head ---
    k_transpose<<<(HH * HH) / TPB, TPB>>>(Wb);
    k_pool<<<BBG, HH>>>((const float*)p_h, pred);
    k_tp<<<BBG, HH>>>();
    k_score<<<BBG, HH>>>((const float*)p_h, pred, bb, out);
}

// round 6
// speedup vs baseline: 1.9344x; 1.3486x over previous
#include <cuda_runtime.h>
#include <cuda_bf16.h>
#include <cstdint>

#define NN   131072
#define EE   1048576
#define HH   128
#define BBG  512
#define PPG  32
#define NH   (NN*HH)

// ---------------- static device scratch ----------------
__device__ float g_emb[NH];
__device__ float g_h[NH];
__device__ float g_h2[NH];
__device__ float g_xinit[NH];
__device__ float g_m[4ULL * NH];   // y[t][N][128]
__device__ float g_pool[BBG * HH];
__device__ float g_tp[BBG * HH];
__device__ float g_wbt[HH * HH];
// dst-keyed CSR
__device__ int  g_cnt[NN];
__device__ int  g_off[NN + 1];
__device__ int  g_cur[NN];
__device__ int  g_bsum[128];
__device__ int2 g_rec[EE];         // {src | etype<<20, norm bits}

// ---------------- helpers ----------------
__device__ __forceinline__ uint32_t smem_u32(const void* p) {
    uint32_t a;
    asm("{ .reg .u64 t; cvta.to.shared.u64 t, %1; cvt.u32.u64 %0, t; }" : "=r"(a) : "l"(p));
    return a;
}
__device__ __forceinline__ void ldsm_x4(uint32_t r[4], uint32_t addr) {
    asm volatile("ldmatrix.sync.aligned.m8n8.x4.shared.b16 {%0,%1,%2,%3}, [%4];"
                 : "=r"(r[0]), "=r"(r[1]), "=r"(r[2]), "=r"(r[3]) : "r"(addr));
}
__device__ __forceinline__ void ldsm_x4_t(uint32_t r[4], uint32_t addr) {
    asm volatile("ldmatrix.sync.aligned.m8n8.x4.trans.shared.b16 {%0,%1,%2,%3}, [%4];"
                 : "=r"(r[0]), "=r"(r[1]), "=r"(r[2]), "=r"(r[3]) : "r"(addr));
}
__device__ __forceinline__ void mma_bf16(float* c, const uint32_t a[4], const uint32_t* b) {
    asm volatile(
        "mma.sync.aligned.m16n8k16.row.col.f32.bf16.bf16.f32 "
        "{%0,%1,%2,%3}, {%4,%5,%6,%7}, {%8,%9}, {%0,%1,%2,%3};"
        : "+f"(c[0]), "+f"(c[1]), "+f"(c[2]), "+f"(c[3])
        : "r"(a[0]), "r"(a[1]), "r"(a[2]), "r"(a[3]), "r"(b[0]), "r"(b[1]));
}
__device__ __forceinline__ void split2(float a, float b, uint32_t& hi, uint32_t& lo) {
    __nv_bfloat16 ha = __float2bfloat16_rn(a);
    __nv_bfloat16 hb = __float2bfloat16_rn(b);
    __nv_bfloat16 la = __float2bfloat16_rn(a - __bfloat162float(ha));
    __nv_bfloat16 lb = __float2bfloat16_rn(b - __bfloat162float(hb));
    hi = (uint32_t)__bfloat16_as_ushort(ha) | ((uint32_t)__bfloat16_as_ushort(hb) << 16);
    lo = (uint32_t)__bfloat16_as_ushort(la) | ((uint32_t)__bfloat16_as_ushort(lb) << 16);
}

// ---------------- CSR build (dst-keyed) ----------------
__global__ void k_count(const int* __restrict__ dst) {
    int e = blockIdx.x * blockDim.x + threadIdx.x;
    if (e >= EE) return;
    atomicAdd(&g_cnt[dst[e]], 1);
}

__global__ void k_scan1() {   // 128 blocks x 256 thr; 1024 elems/block
    __shared__ int s[256];
    int t = threadIdx.x;
    int4 v = *(const int4*)(g_cnt + blockIdx.x * 1024 + t * 4);
    s[t] = v.x + v.y + v.z + v.w;
    __syncthreads();
    for (int o = 128; o > 0; o >>= 1) {
        if (t < o) s[t] += s[t + o];
        __syncthreads();
    }
    if (t == 0) g_bsum[blockIdx.x] = s[0];
}

__global__ void k_scan2() {   // 1 block, 128 thr: exclusive scan
    __shared__ int s[128];
    int t = threadIdx.x;
    int mine = g_bsum[t];
    s[t] = mine;
    __syncthreads();
    for (int o = 1; o < 128; o <<= 1) {
        int add = (t >= o) ? s[t - o] : 0;
        __syncthreads();
        s[t] += add;
        __syncthreads();
    }
    g_bsum[t] = s[t] - mine;
}

__global__ void k_scan3() {   // 128 blocks x 256 thr
    __shared__ int s[256];
    int t = threadIdx.x;
    int base = blockIdx.x * 1024 + t * 4;
    int4 v = *(const int4*)(g_cnt + base);
    int tsum = v.x + v.y + v.z + v.w;
    s[t] = tsum;
    __syncthreads();
    for (int o = 1; o < 256; o <<= 1) {
        int add = (t >= o) ? s[t - o] : 0;
        __syncthreads();
        s[t] += add;
        __syncthreads();
    }
    int o0 = s[t] - tsum + g_bsum[blockIdx.x];
    int o1 = o0 + v.x, o2 = o1 + v.y, o3 = o2 + v.z;
    *(int4*)(g_off + base) = make_int4(o0, o1, o2, o3);
    *(int4*)(g_cur + base) = make_int4(o0, o1, o2, o3);
    if (base + 4 == NN) g_off[NN] = o3 + v.w;
}

__global__ void k_fill(const int* __restrict__ src, const int* __restrict__ dst,
                       const int* __restrict__ et,  const float* __restrict__ norm) {
    int e = blockIdx.x * blockDim.x + threadIdx.x;
    if (e >= EE) return;
    int p = atomicAdd(&g_cur[dst[e]], 1);
    g_rec[p] = make_int2(src[e] | (et[e] << 20), __float_as_int(norm[e]));
}

// ---------------- init_forward + xinit (warp per node, CSR) ----------------
__global__ void k_init(const float4* __restrict__ tab, const int* __restrict__ gid,
                       const int* __restrict__ spo, const int* __restrict__ acc_,
                       const int* __restrict__ pre, const float* __restrict__ Wt,
                       const float* __restrict__ bt)
{
    int node = (blockIdx.x * blockDim.x + threadIdx.x) >> 5;
    int lane = threadIdx.x & 31;
    if (node >= NN) return;
    int s0 = spo[node * 3 + 0];
    int s1 = spo[node * 3 + 1];
    int s2 = spo[node * 3 + 2];
    int beg = g_off[node], end = g_off[node + 1];

    float4 a = make_float4(0.f, 0.f, 0.f, 0.f);
    bool has_ne = false;
    for (int base = beg; base < end; base += 32) {
        int n = min(32, end - base);
        int2 r = (base + lane < end) ? g_rec[base + lane] : make_int2(-1, 0);
        for (int i = 0; i < n; i++) {
            int rx = __shfl_sync(0xffffffffu, r.x, i);
            int rn = __shfl_sync(0xffffffffu, r.y, i);
            if ((rx >> 20) != 0) continue;   // ne edges only (type 0)
            has_ne = true;
            int s = rx & 0xFFFFF;
            float nw = __int_as_float(rn);
            float4 hv = tab[(size_t)gid[s] * 32 + lane];
            a.x += hv.x * nw; a.y += hv.y * nw;
            a.z += hv.z * nw; a.w += hv.w * nw;
        }
    }
    float4 e4;
    if ((s0 + s2) > 0 && has_ne) e4 = a;
    else                         e4 = tab[(size_t)gid[node] * 32 + lane];
    ((float4*)g_emb)[(size_t)node * 32 + lane] = e4;

    float coef[5];
    coef[0] = (float)s0; coef[1] = (float)s1; coef[2] = (float)s2;
    coef[3] = (float)acc_[node]; coef[4] = (float)pre[node];
    float4 r = ((const float4*)bt)[lane];
#pragma unroll
    for (int j = 0; j < 5; j++) {
        float4 ww = ((const float4*)(Wt + (size_t)(128 + j) * HH))[lane];
        r.x += coef[j] * ww.x; r.y += coef[j] * ww.y;
        r.z += coef[j] * ww.z; r.w += coef[j] * ww.w;
    }
    ((float4*)g_xinit)[(size_t)node * 32 + lane] = r;
}

// ---------------- dense HMMA GEMM (input projection) ----------------
#define SM_AHI 0
#define SM_ALO 18432
#define SM_BHI 36864
#define SM_BLO 54272
#define SM_TOT 71680

__global__ void __launch_bounds__(256, 2) k_gemm_tc(
    const float* __restrict__ A, const float* __restrict__ B, int nkc,
    const float* __restrict__ Cadd, float* __restrict__ C)
{
    extern __shared__ char smem[];
    uint32_t s0 = smem_u32(smem);
    int tid = threadIdx.x, wid = tid >> 5, lane = tid & 31;
    int row0 = blockIdx.x * 128;
    int warp_m = wid & 1, warp_n = wid >> 1;

    float c[4][4][4];
#pragma unroll
    for (int i = 0; i < 4; i++)
#pragma unroll
        for (int j = 0; j < 4; j++)
#pragma unroll
            for (int q = 0; q < 4; q++) c[i][j][q] = 0.0f;

    for (int ch = 0; ch < nkc; ch++) {
        if (tid < 128) {
            const float* ga = A + (size_t)row0 * HH + ch * 64;
#pragma unroll
            for (int p = 0; p < 16; p++) {
                int e = p * 128 + tid;
                int r = e >> 4, c4 = e & 15;
                float4 v = *(const float4*)(ga + (size_t)r * HH + c4 * 4);
                uint32_t h0, l0, h1, l1;
                split2(v.x, v.y, h0, l0);
                split2(v.z, v.w, h1, l1);
                uint32_t off = (uint32_t)r * 144 + c4 * 8;
                *(uint2*)(smem + SM_AHI + off) = make_uint2(h0, h1);
                *(uint2*)(smem + SM_ALO + off) = make_uint2(l0, l1);
            }
        } else {
            int t = tid - 128;
            const float* gb = B + (size_t)(ch * 64) * HH;
#pragma unroll
            for (int p = 0; p < 16; p++) {
                int e = p * 128 + t;
                int k = e >> 5, c4 = e & 31;
                float4 v = *(const float4*)(gb + (size_t)k * HH + c4 * 4);
                uint32_t h0, l0, h1, l1;
                split2(v.x, v.y, h0, l0);
                split2(v.z, v.w, h1, l1);
                uint32_t off = (uint32_t)k * 272 + c4 * 8;
                *(uint2*)(smem + SM_BHI + off) = make_uint2(h0, h1);
                *(uint2*)(smem + SM_BLO + off) = make_uint2(l0, l1);
            }
        }
        __syncthreads();

#pragma unroll
        for (int ks = 0; ks < 4; ks++) {
            uint32_t ah[4][4], al[4][4];
#pragma unroll
            for (int mt = 0; mt < 4; mt++) {
                uint32_t row  = warp_m * 64 + mt * 16 + (lane & 15);
                uint32_t addr = s0 + SM_AHI + row * 144 + ks * 32 + ((lane >> 4) << 4);
                ldsm_x4(ah[mt], addr);
                ldsm_x4(al[mt], addr + (SM_ALO - SM_AHI));
            }
#pragma unroll
            for (int np = 0; np < 2; np++) {
                uint32_t kk   = ks * 16 + (lane & 15);
                uint32_t col  = warp_n * 32 + np * 16 + ((lane >> 4) & 1) * 8;
                uint32_t addr = s0 + SM_BHI + kk * 272 + col * 2;
                uint32_t bh[4], bl[4];
                ldsm_x4_t(bh, addr);
                ldsm_x4_t(bl, addr + (SM_BLO - SM_BHI));
#pragma unroll
                for (int mt = 0; mt < 4; mt++) {
                    mma_bf16(c[mt][np * 2],     ah[mt], bh);
                    mma_bf16(c[mt][np * 2],     al[mt], bh);
                    mma_bf16(c[mt][np * 2],     ah[mt], bl);
                    mma_bf16(c[mt][np * 2 + 1], ah[mt], bh + 2);
                    mma_bf16(c[mt][np * 2 + 1], al[mt], bh + 2);
                    mma_bf16(c[mt][np * 2 + 1], ah[mt], bl + 2);
                }
            }
        }
        __syncthreads();
    }

#pragma unroll
    for (int mt = 0; mt < 4; mt++) {
#pragma unroll
        for (int nt = 0; nt < 4; nt++) {
            int col = warp_n * 32 + nt * 8 + (lane & 3) * 2;
#pragma unroll
            for (int half = 0; half < 2; half++) {
                long row  = row0 + warp_m * 64 + mt * 16 + (lane >> 2) + half * 8;
                long base = row * HH + col;
                float2 v;
                v.x = c[mt][nt][half * 2 + 0];
                v.y = c[mt][nt][half * 2 + 1];
                float2 t = *(const float2*)(Cadd + base);
                v.x += t.x; v.y += t.y;
                *(float2*)(C + base) = v;
            }
        }
    }
}

// ---------------- transform-first: y[t] = h @ W_r[l,t] ----------------
#define FS_AHI 0
#define FS_ALO 34816
#define FS_BHI 69632
#define FS_BLO 104448
#define FS_TOT 139264

__global__ void __launch_bounds__(256, 1) k_gemm4(
    const float* __restrict__ A, const float* __restrict__ Wl, float* __restrict__ y)
{
    extern __shared__ char smem[];
    uint32_t s0 = smem_u32(smem);
    int tid = threadIdx.x, wid = tid >> 5, lane = tid & 31;
    int row0 = blockIdx.x * 128;
    int warp_m = wid & 1, warp_n = wid >> 1;

    {
        const float* ga = A + (size_t)row0 * HH;
#pragma unroll
        for (int p = 0; p < 16; p++) {
            int e = p * 256 + tid;
            int r = e >> 5, c4 = e & 31;
            float4 v = *(const float4*)(ga + (size_t)r * HH + c4 * 4);
            uint32_t h0, l0, h1, l1;
            split2(v.x, v.y, h0, l0);
            split2(v.z, v.w, h1, l1);
            uint32_t off = (uint32_t)r * 272 + c4 * 8;
            *(uint2*)(smem + FS_AHI + off) = make_uint2(h0, h1);
            *(uint2*)(smem + FS_ALO + off) = make_uint2(l0, l1);
        }
    }
    __syncthreads();

    for (int t = 0; t < 4; t++) {
        const float* gb = Wl + (size_t)t * HH * HH;
#pragma unroll
        for (int p = 0; p < 16; p++) {
            int e = p * 256 + tid;
            int k = e >> 5, c4 = e & 31;
            float4 v = *(const float4*)(gb + (size_t)k * HH + c4 * 4);
            uint32_t h0, l0, h1, l1;
            split2(v.x, v.y, h0, l0);
            split2(v.z, v.w, h1, l1);
            uint32_t off = (uint32_t)k * 272 + c4 * 8;
            *(uint2*)(smem + FS_BHI + off) = make_uint2(h0, h1);
            *(uint2*)(smem + FS_BLO + off) = make_uint2(l0, l1);
        }
        __syncthreads();

        float c[4][4][4];
#pragma unroll
        for (int i = 0; i < 4; i++)
#pragma unroll
            for (int j = 0; j < 4; j++)
#pragma unroll
                for (int q = 0; q < 4; q++) c[i][j][q] = 0.0f;

#pragma unroll
        for (int ks = 0; ks < 8; ks++) {
            uint32_t ah[4][4], al[4][4];
#pragma unroll
            for (int mt = 0; mt < 4; mt++) {
                uint32_t row  = warp_m * 64 + mt * 16 + (lane & 15);
                uint32_t addr = s0 + FS_AHI + row * 272 + ks * 32 + ((lane >> 4) << 4);
                ldsm_x4(ah[mt], addr);
                ldsm_x4(al[mt], addr + (FS_ALO - FS_AHI));
            }
#pragma unroll
            for (int np = 0; np < 2; np++) {
                uint32_t kk   = ks * 16 + (lane & 15);
                uint32_t col  = warp_n * 32 + np * 16 + ((lane >> 4) & 1) * 8;
                uint32_t addr = s0 + FS_BHI + kk * 272 + col * 2;
                uint32_t bh[4], bl[4];
                ldsm_x4_t(bh, addr);
                ldsm_x4_t(bl, addr + (FS_BLO - FS_BHI));
#pragma unroll
                for (int mt = 0; mt < 4; mt++) {
                    mma_bf16(c[mt][np * 2],     ah[mt], bh);
                    mma_bf16(c[mt][np * 2],     al[mt], bh);
                    mma_bf16(c[mt][np * 2],     ah[mt], bl);
                    mma_bf16(c[mt][np * 2 + 1], ah[mt], bh + 2);
                    mma_bf16(c[mt][np * 2 + 1], al[mt], bh + 2);
                    mma_bf16(c[mt][np * 2 + 1], ah[mt], bl + 2);
                }
            }
        }

        float* Ct = y + (size_t)t * NH;
#pragma unroll
        for (int mt = 0; mt < 4; mt++) {
#pragma unroll
            for (int nt = 0; nt < 4; nt++) {
                int col = warp_n * 32 + nt * 8 + (lane & 3) * 2;
#pragma unroll
                for (int half = 0; half < 2; half++) {
                    long row  = row0 + warp_m * 64 + mt * 16 + (lane >> 2) + half * 8;
                    long base = row * HH + col;
                    *(float2*)(Ct + base) =
                        make_float2(c[mt][nt][half * 2 + 0], c[mt][nt][half * 2 + 1]);
                }
            }
        }
        __syncthreads();
    }
}

// ---------------- CSR gather + bias + relu + residual (warp per dst node) ------
__global__ void k_gather_agg(const float* __restrict__ y, const float* __restrict__ bias,
                             const float* __restrict__ resid, float* __restrict__ out)
{
    int node = (blockIdx.x * blockDim.x + threadIdx.x) >> 5;
    int lane = threadIdx.x & 31;
    if (node >= NN) return;
    int beg = g_off[node], end = g_off[node + 1];

    float4 a = make_float4(0.f, 0.f, 0.f, 0.f);
    for (int base = beg; base < end; base += 32) {
        int n = min(32, end - base);
        int2 r = (base + lane < end) ? g_rec[base + lane] : make_int2(0, 0);
        for (int i = 0; i < n; i++) {
            int rx = __shfl_sync(0xffffffffu, r.x, i);
            int rn = __shfl_sync(0xffffffffu, r.y, i);
            int s = rx & 0xFFFFF;
            int t = rx >> 20;
            float nw = __int_as_float(rn);
            float4 v = *(const float4*)(y + (size_t)t * NH + (size_t)s * HH + lane * 4);
            a.x += v.x * nw; a.y += v.y * nw;
            a.z += v.z * nw; a.w += v.w * nw;
        }
    }
    float4 b = ((const float4*)bias)[lane];
    float4 v;
    v.x = fmaxf(a.x + b.x, 0.f);
    v.y = fmaxf(a.y + b.y, 0.f);
    v.z = fmaxf(a.z + b.z, 0.f);
    v.w = fmaxf(a.w + b.w, 0.f);
    if (resid) {
        float4 rr = ((const float4*)resid)[(size_t)node * 32 + lane];
        v.x += rr.x; v.y += rr.y; v.z += rr.z; v.w += rr.w;
    }
    ((float4*)out)[(size_t)node * 32 + lane] = v;
}

// ---------------- head kernels ----------------
__global__ void k_transpose(const float* __restrict__ Wb) {
    int idx = blockIdx.x * blockDim.x + threadIdx.x;
    if (idx >= HH * HH) return;
    int r = idx >> 7, c = idx & 127;
    g_wbt[c * HH + r] = Wb[idx];
}

__global__ void k_pool(const float* __restrict__ h, const int* __restrict__ pred) {
    int b = blockIdx.x, j = threadIdx.x;
    float acc = 0.0f;
#pragma unroll 4
    for (int p = 0; p < PPG; p++) {
        int node = pred[b * PPG + p];
        acc += h[(size_t)node * HH + j];
    }
    g_pool[b * HH + j] = acc * (1.0f / PPG);
}

__global__ void k_tp() {
    int b = blockIdx.x, hrow = threadIdx.x;
    __shared__ float ps[HH];
    ps[hrow] = g_pool[b * HH + hrow];
    __syncthreads();
    float acc = 0.0f;
#pragma unroll 8
    for (int k = 0; k < HH; k++)
        acc += g_wbt[(size_t)k * HH + hrow] * ps[k];
    g_tp[b * HH + hrow] = acc;
}

__global__ void k_score(const float* __restrict__ h, const int* __restrict__ pred,
                        const float* __restrict__ bbp, float* __restrict__ out)
{
    int b = blockIdx.x;
    int tid = threadIdx.x;
    __shared__ __align__(16) float tps[HH];
    __shared__ float sc[PPG];
    tps[tid] = g_tp[b * HH + tid];
    __syncthreads();
    int warp = tid >> 5, lane = tid & 31;
    float4 tv = ((const float4*)tps)[lane];
    for (int p = warp; p < PPG; p += 4) {
        int node = pred[b * PPG + p];
        float4 hv = ((const float4*)h)[(size_t)node * 32 + lane];
        float d = hv.x * tv.x + hv.y * tv.y + hv.z * tv.z + hv.w * tv.w;
#pragma unroll
        for (int o = 16; o > 0; o >>= 1) d += __shfl_xor_sync(0xffffffffu, d, o);
        if (lane == 0) sc[p] = d + bbp[0];
    }
    __syncthreads();
    if (tid < 32) {
        float v = sc[tid];
        float m = v;
#pragma unroll
        for (int o = 16; o > 0; o >>= 1) m = fmaxf(m, __shfl_xor_sync(0xffffffffu, m, o));
        float e = expf(v - m);
        float s = e;
#pragma unroll
        for (int o = 16; o > 0; o >>= 1) s += __shfl_xor_sync(0xffffffffu, s, o);
        out[b * PPG + tid] = v - m - logf(s);
    }
}

// ---------------- launch ----------------
extern "C" void kernel_launch(void* const* d_in, const int* in_sizes, int n_in,
                              void* d_out, int out_size)
{
    (void)in_sizes; (void)n_in; (void)out_size;
    const float* emb_table = (const float*)d_in[0];
    const float* W_t       = (const float*)d_in[1];
    const float* b_t       = (const float*)d_in[2];
    const float* W_r       = (const float*)d_in[3];
    const float* b_r       = (const float*)d_in[4];
    const float* Wb        = (const float*)d_in[5];
    const float* bb        = (const float*)d_in[6];
    const float* norm      = (const float*)d_in[7];
    const int*   gid       = (const int*)d_in[8];
    const int*   spo       = (const int*)d_in[9];
    const int*   access_   = (const int*)d_in[10];
    const int*   pre       = (const int*)d_in[11];
    const int*   src       = (const int*)d_in[12];
    const int*   dst       = (const int*)d_in[13];
    const int*   etype     = (const int*)d_in[14];
    const int*   pred      = (const int*)d_in[15];
    float* out = (float*)d_out;

    void *p_cnt, *p_m, *p_emb, *p_h, *p_h2, *p_xinit;
    cudaGetSymbolAddress(&p_cnt,   g_cnt);
    cudaGetSymbolAddress(&p_m,     g_m);
    cudaGetSymbolAddress(&p_emb,   g_emb);
    cudaGetSymbolAddress(&p_h,     g_h);
    cudaGetSymbolAddress(&p_h2,    g_h2);
    cudaGetSymbolAddress(&p_xinit, g_xinit);

    const int TPB = 256;
    const int node_warp_blocks = NN / 8;   // warp per node, 8 warps/block
    const int gemm_blocks      = NN / 128;

    cudaFuncSetAttribute(k_gemm_tc, cudaFuncAttributeMaxDynamicSharedMemorySize, SM_TOT);
    cudaFuncSetAttribute(k_gemm4,   cudaFuncAttributeMaxDynamicSharedMemorySize, FS_TOT);

    // --- CSR build (dst-keyed, reused everywhere) ---
    cudaMemsetAsync(p_cnt, 0, (size_t)NN * sizeof(int), 0);
    k_count<<<EE / TPB, TPB>>>(dst);
    k_scan1<<<128, 256>>>();
    k_scan2<<<1, 128>>>();
    k_scan3<<<128, 256>>>();
    k_fill<<<EE / TPB, TPB>>>(src, dst, etype, norm);

    // --- init_forward + xinit ---
    k_init<<<node_warp_blocks, TPB>>>((const float4*)emb_table, gid, spo, access_, pre,
                                      W_t, b_t);

    // --- input projection ---
    k_gemm_tc<<<gemm_blocks, TPB, SM_TOT>>>((const float*)p_emb, W_t, 2,
                                            (const float*)p_xinit, (float*)p_h);

    // --- layer 0 ---
    k_gemm4<<<gemm_blocks, TPB, FS_TOT>>>((const float*)p_h, W_r, (float*)p_m);
    k_gather_agg<<<node_warp_blocks, TPB>>>((const float*)p_m, b_r,
                                            (const float*)p_h, (float*)p_h2);

    // --- layer 1 ---
    k_gemm4<<<gemm_blocks, TPB, FS_TOT>>>((const float*)p_h2, W_r + 4 * HH * HH, (float*)p_m);
    k_gather_agg<<<node_warp_blocks, TPB>>>((const float*)p_m, b_r + HH,
                                            nullptr, (float*)p_h);

    // --- head ---
    k_transpose<<<(HH * HH) / TPB, TPB>>>(Wb);
    k_pool<<<BBG, HH>>>((const float*)p_h, pred);
    k_tp<<<BBG, HH>>>();
    k_score<<<BBG, HH>>>((const float*)p_h, pred, bb, out);
}